// round 10
// baseline (speedup 1.0000x reference)
#include <cuda_runtime.h>

#define DT 0.025f
#define NTHREADS 128
#define ROW 13
#define RPC (NTHREADS * 2)                    // rows per CTA = 256
#define CTA_FLOATS (RPC * ROW)                // 3328
#define CTA_VEC4   (CTA_FLOATS / 4)           // 832

// Branch-free accurate sincos (matched Cody-Waite pair, ~1ulp for |x|<1e3)
__device__ __forceinline__ void fast_sincos(float x, float* s_out, float* c_out)
{
    float k = rintf(x * 0.6366197723675814f);
    int   q = (int)k;
    float r = fmaf(-k, 1.5707963705062866f, x);   // hi = 0x3FC90FDB
    r       = fmaf(k, 4.3711388286e-8f, r);       // lo = -4.37113883e-8
    float r2 = r * r;
    float sinr = fmaf(r * r2, fmaf(r2, fmaf(r2, -1.9841270e-4f, 8.3333338e-3f),
                             -1.6666667e-1f), r);
    float cosr = fmaf(r2, fmaf(r2, fmaf(r2, fmaf(r2, 2.4801587e-5f,
                               -1.3888889e-3f), 4.1666668e-2f), -5.0e-1f), 1.f);
    bool swap = q & 1;
    float ss = swap ? cosr : sinr;
    float cc = swap ? sinr : cosr;
    *s_out = ((q & 3) >= 2) ? -ss : ss;
    *c_out = (((q + 1) & 3) >= 2) ? -cc : cc;
}

struct InvI { float i00, i01, i02, i11, i12, i22, inv_mass; };

__device__ __forceinline__ void compute_row(
    const InvI& C, const float* __restrict__ s,
    float4 aA, float4 aB, float4 aC,
    float4 fA, float4 fB, float4 fC,
    int4 fc4, float* __restrict__ o)
{
    float s0 = s[0],  s1 = s[1],  s2 = s[2];
    float s6 = s[6],  s7 = s[7],  s8 = s[8];

    float sr, cr, sp, cp, sy, cy;
    __sincosf(s0, &sr, &cr);
    fast_sincos(s1, &sp, &cp);      // pitch precise: feeds 1/cp
    __sincosf(s2, &sy, &cy);

    float R00 = cy*cp, R01 = cy*sp*sr - sy*cr, R02 = cy*sp*cr + sy*sr;
    float R10 = sy*cp, R11 = sy*sp*sr + cy*cr, R12 = sy*sp*cr - cy*sr;
    float R20 = -sp,   R21 = cp*sr,            R22 = cp*cr;
    float rcp_cp = __fdividef(1.0f, cp);

    float ax[4] = { aA.x, aA.w, aB.z, aC.y };
    float ay[4] = { aA.y, aB.x, aB.w, aC.z };
    float az[4] = { aA.z, aB.y, aC.x, aC.w };
    float px[4] = { fA.x, fA.w, fB.z, fC.y };
    float py[4] = { fA.y, fB.x, fB.w, fC.z };
    float pz[4] = { fA.z, fB.y, fC.x, fC.w };
    float fcw[4] = { (float)(fc4.x != 0), (float)(fc4.y != 0),
                     (float)(fc4.z != 0), (float)(fc4.w != 0) };

    float wx = 0.f, wy = 0.f, wz = 0.f, Fx = 0.f, Fy = 0.f, Fz = 0.f;
    #pragma unroll
    for (int f = 0; f < 4; f++) {
        float vx = R00*px[f] + R01*py[f] + R02*pz[f];
        float vy = R10*px[f] + R11*py[f] + R12*pz[f];
        float vz = R20*px[f] + R21*py[f] + R22*pz[f];
        wx += fcw[f] * (vy*az[f] - vz*ay[f]);
        wy += fcw[f] * (vz*ax[f] - vx*az[f]);
        wz += fcw[f] * (vx*ay[f] - vy*ax[f]);
        Fx += fcw[f] * ax[f];
        Fy += fcw[f] * ay[f];
        Fz += fcw[f] * az[f];
    }

    float ux = R00*wx + R10*wy + R20*wz;
    float uy = R01*wx + R11*wy + R21*wz;
    float uz = R02*wx + R12*wy + R22*wz;
    float vx = C.i00*ux + C.i01*uy + C.i02*uz;
    float vy = C.i01*ux + C.i11*uy + C.i12*uz;
    float vz = C.i02*ux + C.i12*uy + C.i22*uz;
    float tx = R00*vx + R01*vy + R02*vz;
    float ty = R10*vx + R11*vy + R12*vz;
    float tz = R20*vx + R21*vy + R22*vz;

    float m0 = cy*s6 + sy*s7;
    o[0]  = s0 + DT * (m0 * rcp_cp);
    o[1]  = s1 + DT * (cy*s7 - sy*s6);
    o[2]  = s2 + DT * (m0 * sp * rcp_cp + s8);
    o[3]  = s[3] + DT * s[9];
    o[4]  = s[4] + DT * s[10];
    o[5]  = s[5] + DT * s[11];
    o[6]  = s6 + DT * tx;
    o[7]  = s7 + DT * ty;
    o[8]  = s8 + DT * tz;
    o[9]  = s[9]  + DT * C.inv_mass * Fx;
    o[10] = s[10] + DT * C.inv_mass * Fy;
    o[11] = s[11] + DT * (C.inv_mass * Fz + s[12]);
    o[12] = s[12];
}

__global__ void __launch_bounds__(NTHREADS, 5)
get_next_states_kernel(const float* __restrict__ params,
                       const float* __restrict__ states,
                       const float* __restrict__ actions,
                       const float* __restrict__ foot_pos,
                       const int* __restrict__ foot_contacts,
                       float* __restrict__ out,
                       int n)
{
    __shared__ float sbuf[CTA_FLOATS];

    int tid = threadIdx.x;
    int blockBase = blockIdx.x * RPC;
    int i0 = blockBase + tid;
    int i1 = i0 + NTHREADS;
    bool fullBlock = (blockBase + RPC) <= n;

    float p0 = __ldg(params + 0);
    float p1 = __ldg(params + 1);
    float p2 = __ldg(params + 2);
    float p3 = __ldg(params + 3);
    float p4 = __ldg(params + 4);
    float p5 = __ldg(params + 5);
    float p6 = __ldg(params + 6);

    // ---- issue all 14 independent per-row vector loads up front (MLP) ----
    float4 aA0, aB0, aC0, fA0, fB0, fC0, aA1, aB1, aC1, fA1, fB1, fC1;
    int4 fc0 = make_int4(0,0,0,0), fc1 = make_int4(0,0,0,0);
    float4 z4 = make_float4(0.f,0.f,0.f,0.f);
    aA0=aB0=aC0=fA0=fB0=fC0=aA1=aB1=aC1=fA1=fB1=fC1=z4;
    if (i0 < n) {
        const float4* a4 = (const float4*)(actions  + (size_t)i0 * 12);
        const float4* f4 = (const float4*)(foot_pos + (size_t)i0 * 12);
        aA0 = a4[0]; aB0 = a4[1]; aC0 = a4[2];
        fA0 = f4[0]; fB0 = f4[1]; fC0 = f4[2];
        fc0 = *(const int4*)(foot_contacts + (size_t)i0 * 4);
    }
    if (i1 < n) {
        const float4* a4 = (const float4*)(actions  + (size_t)i1 * 12);
        const float4* f4 = (const float4*)(foot_pos + (size_t)i1 * 12);
        aA1 = a4[0]; aB1 = a4[1]; aC1 = a4[2];
        fA1 = f4[0]; fB1 = f4[1]; fC1 = f4[2];
        fc1 = *(const int4*)(foot_contacts + (size_t)i1 * 4);
    }

    // ---- cooperative coalesced staging of 256 state rows ----
    float sA[ROW], sB[ROW];
    if (fullBlock) {
        const float4* src = (const float4*)(states + (size_t)blockBase * ROW);
        float4* dst = (float4*)sbuf;
        #pragma unroll
        for (int j = 0; j < 7; j++) {
            int idx = tid + j * NTHREADS;
            if (idx < CTA_VEC4) dst[idx] = src[idx];
        }
        __syncthreads();
        #pragma unroll
        for (int k = 0; k < ROW; k++) sA[k] = sbuf[tid * ROW + k];
        #pragma unroll
        for (int k = 0; k < ROW; k++) sB[k] = sbuf[(tid + NTHREADS) * ROW + k];
    } else {
        const float* sp0 = states + (size_t)i0 * ROW;
        const float* sp1 = states + (size_t)i1 * ROW;
        #pragma unroll
        for (int k = 0; k < ROW; k++) sA[k] = (i0 < n) ? sp0[k] : 0.f;
        #pragma unroll
        for (int k = 0; k < ROW; k++) sB[k] = (i1 < n) ? sp1[k] : 0.f;
    }

    // ---- shared per-thread constants ----
    InvI C;
    C.inv_mass = __fdividef(1.0f, p0);
    float I00 = p1*p1 + 1e-5f;
    float I01 = p1*p2 + 1e-5f;
    float I02 = p1*p4 + 1e-5f;
    float I11 = p2*p2 + p3*p3 + 1e-5f;
    float I12 = p2*p4 + p3*p5 + 1e-5f;
    float I22 = p4*p4 + p5*p5 + p6*p6 + 1e-5f;
    float c00 = I11*I22 - I12*I12;
    float c01 = I02*I12 - I01*I22;
    float c02 = I01*I12 - I02*I11;
    float det = I00*c00 + I01*c01 + I02*c02;
    float invdet = __fdividef(1.0f, det);
    C.i00 = c00 * invdet;
    C.i01 = c01 * invdet;
    C.i02 = c02 * invdet;
    C.i11 = (I00*I22 - I02*I02) * invdet;
    C.i12 = (I02*I01 - I00*I12) * invdet;
    C.i22 = (I00*I11 - I01*I01) * invdet;

    float oA[ROW], oB[ROW];
    compute_row(C, sA, aA0, aB0, aC0, fA0, fB0, fC0, fc0, oA);
    compute_row(C, sB, aA1, aB1, aC1, fA1, fB1, fC1, fc1, oB);

    if (fullBlock) {
        __syncthreads();     // staging reads done before overwrite
        #pragma unroll
        for (int k = 0; k < ROW; k++) sbuf[tid * ROW + k] = oA[k];
        #pragma unroll
        for (int k = 0; k < ROW; k++) sbuf[(tid + NTHREADS) * ROW + k] = oB[k];
        __syncthreads();
        float4* dst = (float4*)(out + (size_t)blockBase * ROW);
        const float4* src = (const float4*)sbuf;
        #pragma unroll
        for (int j = 0; j < 7; j++) {
            int idx = tid + j * NTHREADS;
            if (idx < CTA_VEC4) dst[idx] = src[idx];
        }
    } else {
        if (i0 < n) {
            float* o = out + (size_t)i0 * ROW;
            #pragma unroll
            for (int k = 0; k < ROW; k++) o[k] = oA[k];
        }
        if (i1 < n) {
            float* o = out + (size_t)i1 * ROW;
            #pragma unroll
            for (int k = 0; k < ROW; k++) o[k] = oB[k];
        }
    }
}

extern "C" void kernel_launch(void* const* d_in, const int* in_sizes, int n_in,
                              void* d_out, int out_size) {
    const float* params   = (const float*)d_in[0];
    const float* states   = (const float*)d_in[1];
    const float* actions  = (const float*)d_in[2];
    const float* foot_pos = (const float*)d_in[3];
    const int*   foot_contacts = (const int*)d_in[4];
    float* out = (float*)d_out;

    int n = in_sizes[1] / 13;
    int blocks = (n + RPC - 1) / RPC;
    get_next_states_kernel<<<blocks, NTHREADS>>>(params, states, actions,
                                                 foot_pos, foot_contacts, out, n);
}

// round 11
// speedup vs baseline: 1.0150x; 1.0150x over previous
#include <cuda_runtime.h>

#define DT 0.025f
#define NTHREADS 128
#define ROW 13
#define BLK_FLOATS (NTHREADS * ROW)          // 1664
#define WARP_VEC4  (32 * ROW / 4)            // 104 float4 per warp slice

// Branch-free accurate sincos (matched Cody-Waite pair, ~1ulp for |x|<1e3)
__device__ __forceinline__ void fast_sincos(float x, float* s_out, float* c_out)
{
    float k = rintf(x * 0.6366197723675814f);
    int   q = (int)k;
    float r = fmaf(-k, 1.5707963705062866f, x);   // hi = 0x3FC90FDB
    r       = fmaf(k, 4.3711388286e-8f, r);       // lo = -4.37113883e-8
    float r2 = r * r;
    float sinr = fmaf(r * r2, fmaf(r2, fmaf(r2, -1.9841270e-4f, 8.3333338e-3f),
                             -1.6666667e-1f), r);
    float cosr = fmaf(r2, fmaf(r2, fmaf(r2, fmaf(r2, 2.4801587e-5f,
                               -1.3888889e-3f), 4.1666668e-2f), -5.0e-1f), 1.f);
    bool swap = q & 1;
    float ss = swap ? cosr : sinr;
    float cc = swap ? sinr : cosr;
    *s_out = ((q & 3) >= 2) ? -ss : ss;
    *c_out = (((q + 1) & 3) >= 2) ? -cc : cc;
}

__global__ void __launch_bounds__(NTHREADS, 10)
get_next_states_kernel(const float* __restrict__ params,
                       const float* __restrict__ states,
                       const float* __restrict__ actions,
                       const float* __restrict__ foot_pos,
                       const int* __restrict__ foot_contacts,
                       float* __restrict__ out,
                       int n)
{
    __shared__ float sbuf[BLK_FLOATS];

    int tid  = threadIdx.x;
    int lane = tid & 31;
    int wrp  = tid >> 5;
    int blockBase = blockIdx.x * NTHREADS;
    int i = blockBase + tid;
    bool fullBlock = (blockBase + NTHREADS) <= n;

    float p0 = __ldg(params + 0);
    float p1 = __ldg(params + 1);
    float p2 = __ldg(params + 2);
    float p3 = __ldg(params + 3);
    float p4 = __ldg(params + 4);
    float p5 = __ldg(params + 5);
    float p6 = __ldg(params + 6);

    // ---- per-row vector loads ----
    float4 aA, aB, aC, fA, fB, fC;
    int4 fc4 = make_int4(0, 0, 0, 0);
    if (i < n) {
        const float4* a4 = (const float4*)(actions  + (size_t)i * 12);
        const float4* f4 = (const float4*)(foot_pos + (size_t)i * 12);
        aA = a4[0]; aB = a4[1]; aC = a4[2];
        fA = f4[0]; fB = f4[1]; fC = f4[2];
        fc4 = *(const int4*)(foot_contacts + (size_t)i * 4);
    } else {
        aA = aB = aC = fA = fB = fC = make_float4(0.f, 0.f, 0.f, 0.f);
    }

    // Fold contact mask into actions NOW: cross(v, fc*a) = fc*cross(v,a),
    // F = sum fc*a. Kills the fcw[] array + 12 later multiplies.
    {
        float w0 = (fc4.x != 0) ? 1.f : 0.f;
        float w1 = (fc4.y != 0) ? 1.f : 0.f;
        float w2 = (fc4.z != 0) ? 1.f : 0.f;
        float w3 = (fc4.w != 0) ? 1.f : 0.f;
        aA.x *= w0; aA.y *= w0; aA.z *= w0;
        aA.w *= w1; aB.x *= w1; aB.y *= w1;
        aB.z *= w2; aB.w *= w2; aC.x *= w2;
        aC.y *= w3; aC.z *= w3; aC.w *= w3;
    }

    // ---- states: warp-autonomous coalesced staging ----
    float s0, s1, s2, s3, s4, s5, s6, s7, s8, s9, s10, s11, s12;
    if (fullBlock) {
        const float4* src = (const float4*)(states + (size_t)blockBase * ROW) + wrp * WARP_VEC4;
        float4* dst = (float4*)sbuf + wrp * WARP_VEC4;
        #pragma unroll
        for (int j = 0; j < 4; j++) {
            int idx = lane + j * 32;
            if (idx < WARP_VEC4) dst[idx] = src[idx];
        }
        __syncwarp();
        const float* s = sbuf + tid * ROW;
        s0 = s[0];  s1 = s[1];  s2 = s[2];  s3 = s[3];  s4 = s[4];
        s5 = s[5];  s6 = s[6];  s7 = s[7];  s8 = s[8];  s9 = s[9];
        s10 = s[10]; s11 = s[11]; s12 = s[12];
    } else {
        const float* s = states + (size_t)i * ROW;
        bool v = i < n;
        s0 = v ? s[0] : 0.f;  s1 = v ? s[1] : 0.f;  s2 = v ? s[2] : 0.f;
        s3 = v ? s[3] : 0.f;  s4 = v ? s[4] : 0.f;  s5 = v ? s[5] : 0.f;
        s6 = v ? s[6] : 0.f;  s7 = v ? s[7] : 0.f;  s8 = v ? s[8] : 0.f;
        s9 = v ? s[9] : 0.f;  s10 = v ? s[10] : 0.f; s11 = v ? s[11] : 0.f;
        s12 = v ? s[12] : 0.f;
    }

    // ---- inertia inverse (per-thread, ALU-cheap, broadcast inputs) ----
    float inv_mass = __fdividef(1.0f, p0);
    float I00 = p1*p1 + 1e-5f;
    float I01 = p1*p2 + 1e-5f;
    float I02 = p1*p4 + 1e-5f;
    float I11 = p2*p2 + p3*p3 + 1e-5f;
    float I12 = p2*p4 + p3*p5 + 1e-5f;
    float I22 = p4*p4 + p5*p5 + p6*p6 + 1e-5f;
    float c00 = I11*I22 - I12*I12;
    float c01 = I02*I12 - I01*I22;
    float c02 = I01*I12 - I02*I11;
    float det = I00*c00 + I01*c01 + I02*c02;
    float invdet = __fdividef(1.0f, det);
    float iI00 = c00 * invdet;
    float iI01 = c01 * invdet;
    float iI02 = c02 * invdet;
    float iI11 = (I00*I22 - I02*I02) * invdet;
    float iI12 = (I02*I01 - I00*I12) * invdet;
    float iI22 = (I00*I11 - I01*I01) * invdet;

    // trig: MUFU roll/yaw; precise branch-free CW for pitch (feeds 1/cp)
    float sr, cr, sp, cp, sy, cy;
    __sincosf(s0, &sr, &cr);
    fast_sincos(s1, &sp, &cp);
    __sincosf(s2, &sy, &cy);

    float R00 = cy*cp, R01 = cy*sp*sr - sy*cr, R02 = cy*sp*cr + sy*sr;
    float R10 = sy*cp, R11 = sy*sp*sr + cy*cr, R12 = sy*sp*cr - cy*sr;
    float R20 = -sp,   R21 = cp*sr,            R22 = cp*cr;
    float rcp_cp = __fdividef(1.0f, cp);

    float ax[4] = { aA.x, aA.w, aB.z, aC.y };
    float ay[4] = { aA.y, aB.x, aB.w, aC.z };
    float az[4] = { aA.z, aB.y, aC.x, aC.w };
    float px[4] = { fA.x, fA.w, fB.z, fC.y };
    float py[4] = { fA.y, fB.x, fB.w, fC.z };
    float pz[4] = { fA.z, fB.y, fC.x, fC.w };

    // w = sum_f cross(foot_world_f, a_f);  F = sum_f a_f   (a pre-masked)
    float wx = 0.f, wy = 0.f, wz = 0.f, Fx = 0.f, Fy = 0.f, Fz = 0.f;
    #pragma unroll
    for (int f = 0; f < 4; f++) {
        float vx = R00*px[f] + R01*py[f] + R02*pz[f];
        float vy = R10*px[f] + R11*py[f] + R12*pz[f];
        float vz = R20*px[f] + R21*py[f] + R22*pz[f];
        wx += vy*az[f] - vz*ay[f];
        wy += vz*ax[f] - vx*az[f];
        wz += vx*ay[f] - vy*ax[f];
        Fx += ax[f];
        Fy += ay[f];
        Fz += az[f];
    }

    // t = R * invI * R^T * w
    float ux = R00*wx + R10*wy + R20*wz;
    float uy = R01*wx + R11*wy + R21*wz;
    float uz = R02*wx + R12*wy + R22*wz;
    float vx = iI00*ux + iI01*uy + iI02*uz;
    float vy = iI01*ux + iI11*uy + iI12*uz;
    float vz = iI02*ux + iI12*uy + iI22*uz;
    float tx = R00*vx + R01*vy + R02*vz;
    float ty = R10*vx + R11*vy + R12*vz;
    float tz = R20*vx + R21*vy + R22*vz;

    float m0 = cy*s6 + sy*s7;
    float o0  = s0 + DT * (m0 * rcp_cp);
    float o1  = s1 + DT * (cy*s7 - sy*s6);
    float o2  = s2 + DT * (m0 * sp * rcp_cp + s8);
    float o3  = s3 + DT * s9;
    float o4  = s4 + DT * s10;
    float o5  = s5 + DT * s11;
    float o6  = s6 + DT * tx;
    float o7  = s7 + DT * ty;
    float o8  = s8 + DT * tz;
    float o9  = s9  + DT * inv_mass * Fx;
    float o10 = s10 + DT * inv_mass * Fy;
    float o11 = s11 + DT * (inv_mass * Fz + s12);
    float o12 = s12;

    if (fullBlock) {
        float* w13 = sbuf + tid * ROW;
        w13[0] = o0;  w13[1] = o1;  w13[2] = o2;  w13[3] = o3;  w13[4] = o4;
        w13[5] = o5;  w13[6] = o6;  w13[7] = o7;  w13[8] = o8;  w13[9] = o9;
        w13[10] = o10; w13[11] = o11; w13[12] = o12;
        __syncwarp();
        float4* dst = (float4*)(out + (size_t)blockBase * ROW) + wrp * WARP_VEC4;
        const float4* src = (const float4*)sbuf + wrp * WARP_VEC4;
        #pragma unroll
        for (int j = 0; j < 4; j++) {
            int idx = lane + j * 32;
            if (idx < WARP_VEC4) dst[idx] = src[idx];
        }
    } else if (i < n) {
        float* o = out + (size_t)i * ROW;
        o[0] = o0;  o[1] = o1;  o[2] = o2;  o[3] = o3;  o[4] = o4;
        o[5] = o5;  o[6] = o6;  o[7] = o7;  o[8] = o8;  o[9] = o9;
        o[10] = o10; o[11] = o11; o[12] = o12;
    }
}

extern "C" void kernel_launch(void* const* d_in, const int* in_sizes, int n_in,
                              void* d_out, int out_size) {
    const float* params   = (const float*)d_in[0];
    const float* states   = (const float*)d_in[1];
    const float* actions  = (const float*)d_in[2];
    const float* foot_pos = (const float*)d_in[3];
    const int*   foot_contacts = (const int*)d_in[4];
    float* out = (float*)d_out;

    int n = in_sizes[1] / 13;
    int blocks = (n + NTHREADS - 1) / NTHREADS;
    get_next_states_kernel<<<blocks, NTHREADS>>>(params, states, actions,
                                                 foot_pos, foot_contacts, out, n);
}

// round 12
// speedup vs baseline: 1.1871x; 1.1696x over previous
#include <cuda_runtime.h>
#include <cuda_pipeline.h>

#define DT 0.025f
#define NTHREADS 128
#define ROW 13
#define TILE_FLOATS (NTHREADS * ROW)         // 1664 floats per tile
#define WARP_VEC4   (32 * ROW / 4)           // 104 float4 per warp slice

// Branch-free accurate sincos (matched Cody-Waite pair, ~1ulp for |x|<1e3)
__device__ __forceinline__ void fast_sincos(float x, float* s_out, float* c_out)
{
    float k = rintf(x * 0.6366197723675814f);
    int   q = (int)k;
    float r = fmaf(-k, 1.5707963705062866f, x);   // hi = 0x3FC90FDB
    r       = fmaf(k, 4.3711388286e-8f, r);       // lo = -4.37113883e-8
    float r2 = r * r;
    float sinr = fmaf(r * r2, fmaf(r2, fmaf(r2, -1.9841270e-4f, 8.3333338e-3f),
                             -1.6666667e-1f), r);
    float cosr = fmaf(r2, fmaf(r2, fmaf(r2, fmaf(r2, 2.4801587e-5f,
                               -1.3888889e-3f), 4.1666668e-2f), -5.0e-1f), 1.f);
    bool swap = q & 1;
    float ss = swap ? cosr : sinr;
    float cc = swap ? sinr : cosr;
    *s_out = ((q & 3) >= 2) ? -ss : ss;
    *c_out = (((q + 1) & 3) >= 2) ? -cc : cc;
}

struct Consts { float i00,i01,i02,i11,i12,i22,inv_mass; };

// Process one 128-row tile. sin_buf holds the tile's states if full==true.
__device__ __forceinline__ void process_tile(
    const Consts& C, int rowBase, int n, bool full,
    const float* __restrict__ states,
    const float* __restrict__ actions,
    const float* __restrict__ foot_pos,
    const int*   __restrict__ foot_contacts,
    float* __restrict__ out,
    const float* __restrict__ sin_buf,   // smem, staged states (if full)
    float* __restrict__ obuf,            // smem, output staging
    int tid, int lane, int wrp, int wait_prior)
{
    int i = rowBase + tid;

    // per-row vector loads issued first (overlap with cp.async wait)
    float4 aA, aB, aC, fA, fB, fC;
    int4 fc4 = make_int4(0,0,0,0);
    if (i < n) {
        const float4* a4 = (const float4*)(actions  + (size_t)i * 12);
        const float4* f4 = (const float4*)(foot_pos + (size_t)i * 12);
        aA = a4[0]; aB = a4[1]; aC = a4[2];
        fA = f4[0]; fB = f4[1]; fC = f4[2];
        fc4 = *(const int4*)(foot_contacts + (size_t)i * 4);
    } else {
        aA = aB = aC = fA = fB = fC = make_float4(0.f,0.f,0.f,0.f);
    }
    // fold contact mask into actions: cross(v, fc*a) = fc*cross(v,a)
    {
        float w0 = (fc4.x != 0) ? 1.f : 0.f;
        float w1 = (fc4.y != 0) ? 1.f : 0.f;
        float w2 = (fc4.z != 0) ? 1.f : 0.f;
        float w3 = (fc4.w != 0) ? 1.f : 0.f;
        aA.x *= w0; aA.y *= w0; aA.z *= w0;
        aA.w *= w1; aB.x *= w1; aB.y *= w1;
        aB.z *= w2; aB.w *= w2; aC.x *= w2;
        aC.y *= w3; aC.z *= w3; aC.w *= w3;
    }

    float s0,s1,s2,s3,s4,s5,s6,s7,s8,s9,s10,s11,s12;
    if (full) {
        __pipeline_wait_prior(wait_prior);   // this tile's cp.async done
        __syncwarp();                        // all lanes of this warp done
        const float* s = sin_buf + tid * ROW;
        s0=s[0]; s1=s[1]; s2=s[2]; s3=s[3]; s4=s[4]; s5=s[5]; s6=s[6];
        s7=s[7]; s8=s[8]; s9=s[9]; s10=s[10]; s11=s[11]; s12=s[12];
    } else {
        const float* s = states + (size_t)i * ROW;
        bool v = i < n;
        s0 = v?s[0]:0.f; s1 = v?s[1]:0.f; s2 = v?s[2]:0.f; s3 = v?s[3]:0.f;
        s4 = v?s[4]:0.f; s5 = v?s[5]:0.f; s6 = v?s[6]:0.f; s7 = v?s[7]:0.f;
        s8 = v?s[8]:0.f; s9 = v?s[9]:0.f; s10 = v?s[10]:0.f;
        s11 = v?s[11]:0.f; s12 = v?s[12]:0.f;
    }

    float sr, cr, sp, cp, sy, cy;
    __sincosf(s0, &sr, &cr);
    fast_sincos(s1, &sp, &cp);               // pitch precise: feeds 1/cp
    __sincosf(s2, &sy, &cy);

    float R00 = cy*cp, R01 = cy*sp*sr - sy*cr, R02 = cy*sp*cr + sy*sr;
    float R10 = sy*cp, R11 = sy*sp*sr + cy*cr, R12 = sy*sp*cr - cy*sr;
    float R20 = -sp,   R21 = cp*sr,            R22 = cp*cr;
    float rcp_cp = __fdividef(1.0f, cp);

    float ax[4] = { aA.x, aA.w, aB.z, aC.y };
    float ay[4] = { aA.y, aB.x, aB.w, aC.z };
    float az[4] = { aA.z, aB.y, aC.x, aC.w };
    float px[4] = { fA.x, fA.w, fB.z, fC.y };
    float py[4] = { fA.y, fB.x, fB.w, fC.z };
    float pz[4] = { fA.z, fB.y, fC.x, fC.w };

    float wx=0.f, wy=0.f, wz=0.f, Fx=0.f, Fy=0.f, Fz=0.f;
    #pragma unroll
    for (int f = 0; f < 4; f++) {
        float vx = R00*px[f] + R01*py[f] + R02*pz[f];
        float vy = R10*px[f] + R11*py[f] + R12*pz[f];
        float vz = R20*px[f] + R21*py[f] + R22*pz[f];
        wx += vy*az[f] - vz*ay[f];
        wy += vz*ax[f] - vx*az[f];
        wz += vx*ay[f] - vy*ax[f];
        Fx += ax[f]; Fy += ay[f]; Fz += az[f];
    }

    float ux = R00*wx + R10*wy + R20*wz;
    float uy = R01*wx + R11*wy + R21*wz;
    float uz = R02*wx + R12*wy + R22*wz;
    float vx = C.i00*ux + C.i01*uy + C.i02*uz;
    float vy = C.i01*ux + C.i11*uy + C.i12*uz;
    float vz = C.i02*ux + C.i12*uy + C.i22*uz;
    float tx = R00*vx + R01*vy + R02*vz;
    float ty = R10*vx + R11*vy + R12*vz;
    float tz = R20*vx + R21*vy + R22*vz;

    float m0 = cy*s6 + sy*s7;
    float o0  = s0 + DT * (m0 * rcp_cp);
    float o1  = s1 + DT * (cy*s7 - sy*s6);
    float o2  = s2 + DT * (m0 * sp * rcp_cp + s8);
    float o3  = s3 + DT * s9;
    float o4  = s4 + DT * s10;
    float o5  = s5 + DT * s11;
    float o6  = s6 + DT * tx;
    float o7  = s7 + DT * ty;
    float o8  = s8 + DT * tz;
    float o9  = s9  + DT * C.inv_mass * Fx;
    float o10 = s10 + DT * C.inv_mass * Fy;
    float o11 = s11 + DT * (C.inv_mass * Fz + s12);
    float o12 = s12;

    if (full) {
        float* w13 = obuf + tid * ROW;
        w13[0]=o0; w13[1]=o1; w13[2]=o2; w13[3]=o3; w13[4]=o4; w13[5]=o5;
        w13[6]=o6; w13[7]=o7; w13[8]=o8; w13[9]=o9; w13[10]=o10;
        w13[11]=o11; w13[12]=o12;
        __syncwarp();
        float4* dst = (float4*)(out + (size_t)rowBase * ROW) + wrp * WARP_VEC4;
        const float4* src = (const float4*)obuf + wrp * WARP_VEC4;
        #pragma unroll
        for (int j = 0; j < 4; j++) {
            int idx = lane + j * 32;
            if (idx < WARP_VEC4) dst[idx] = src[idx];
        }
        __syncwarp();   // slice fully drained before obuf reuse by next tile
    } else if (i < n) {
        float* o = out + (size_t)i * ROW;
        o[0]=o0; o[1]=o1; o[2]=o2; o[3]=o3; o[4]=o4; o[5]=o5; o[6]=o6;
        o[7]=o7; o[8]=o8; o[9]=o9; o[10]=o10; o[11]=o11; o[12]=o12;
    }
}

__global__ void __launch_bounds__(NTHREADS, 8)
get_next_states_kernel(const float* __restrict__ params,
                       const float* __restrict__ states,
                       const float* __restrict__ actions,
                       const float* __restrict__ foot_pos,
                       const int* __restrict__ foot_contacts,
                       float* __restrict__ out,
                       int n)
{
    __shared__ __align__(16) float bufA[TILE_FLOATS];
    __shared__ __align__(16) float bufB[TILE_FLOATS];
    __shared__ __align__(16) float obuf[TILE_FLOATS];

    int tid  = threadIdx.x;
    int lane = tid & 31;
    int wrp  = tid >> 5;

    int tile0 = blockIdx.x * 2;
    int tile1 = tile0 + 1;
    int base0 = tile0 * NTHREADS;
    int base1 = tile1 * NTHREADS;
    bool full0 = (base0 + NTHREADS) <= n;
    bool full1 = (base1 + NTHREADS) <= n;

    // ---- prefetch both tiles' states via cp.async (warp-sliced pattern) ----
    if (full0) {
        const float4* src = (const float4*)(states + (size_t)base0 * ROW) + wrp * WARP_VEC4;
        float4* dst = (float4*)bufA + wrp * WARP_VEC4;
        #pragma unroll
        for (int j = 0; j < 4; j++) {
            int idx = lane + j * 32;
            if (idx < WARP_VEC4) __pipeline_memcpy_async(&dst[idx], &src[idx], 16);
        }
    }
    __pipeline_commit();
    if (full1) {
        const float4* src = (const float4*)(states + (size_t)base1 * ROW) + wrp * WARP_VEC4;
        float4* dst = (float4*)bufB + wrp * WARP_VEC4;
        #pragma unroll
        for (int j = 0; j < 4; j++) {
            int idx = lane + j * 32;
            if (idx < WARP_VEC4) __pipeline_memcpy_async(&dst[idx], &src[idx], 16);
        }
    }
    __pipeline_commit();

    // ---- per-thread constants ----
    float p0 = __ldg(params + 0);
    float p1 = __ldg(params + 1);
    float p2 = __ldg(params + 2);
    float p3 = __ldg(params + 3);
    float p4 = __ldg(params + 4);
    float p5 = __ldg(params + 5);
    float p6 = __ldg(params + 6);

    Consts C;
    C.inv_mass = __fdividef(1.0f, p0);
    float I00 = p1*p1 + 1e-5f;
    float I01 = p1*p2 + 1e-5f;
    float I02 = p1*p4 + 1e-5f;
    float I11 = p2*p2 + p3*p3 + 1e-5f;
    float I12 = p2*p4 + p3*p5 + 1e-5f;
    float I22 = p4*p4 + p5*p5 + p6*p6 + 1e-5f;
    float c00 = I11*I22 - I12*I12;
    float c01 = I02*I12 - I01*I22;
    float c02 = I01*I12 - I02*I11;
    float det = I00*c00 + I01*c01 + I02*c02;
    float invdet = __fdividef(1.0f, det);
    C.i00 = c00 * invdet;
    C.i01 = c01 * invdet;
    C.i02 = c02 * invdet;
    C.i11 = (I00*I22 - I02*I02) * invdet;
    C.i12 = (I02*I01 - I00*I12) * invdet;
    C.i22 = (I00*I11 - I01*I01) * invdet;

    // tile 0: wait all-but-1 groups (tile1 still streaming)
    if (base0 < n)
        process_tile(C, base0, n, full0, states, actions, foot_pos,
                     foot_contacts, out, bufA, obuf, tid, lane, wrp, 1);
    // tile 1: wait everything
    if (base1 < n)
        process_tile(C, base1, n, full1, states, actions, foot_pos,
                     foot_contacts, out, bufB, obuf, tid, lane, wrp, 0);
}

extern "C" void kernel_launch(void* const* d_in, const int* in_sizes, int n_in,
                              void* d_out, int out_size) {
    const float* params   = (const float*)d_in[0];
    const float* states   = (const float*)d_in[1];
    const float* actions  = (const float*)d_in[2];
    const float* foot_pos = (const float*)d_in[3];
    const int*   foot_contacts = (const int*)d_in[4];
    float* out = (float*)d_out;

    int n = in_sizes[1] / 13;
    int tiles  = (n + NTHREADS - 1) / NTHREADS;
    int blocks = (tiles + 1) / 2;
    get_next_states_kernel<<<blocks, NTHREADS>>>(params, states, actions,
                                                 foot_pos, foot_contacts, out, n);
}